// round 15
// baseline (speedup 1.0000x reference)
#include <cuda_runtime.h>

#define BI 256            // i-rows per block (2 per thread)
#define BJ 64             // j-cols per block (16 iterations of 4 j's)
#define THREADS 128
#define MAX_BLOCKS 2240   // >= 2112 needed for N=8192

// Per-block partial sums + completion counter (no allocations, deterministic).
__device__ double g_partials[MAX_BLOCKS];
__device__ int    g_count = 0;

static __device__ __forceinline__ float ex2_approx(float x) {
    float r; asm("ex2.approx.f32 %0, %1;" : "=f"(r) : "f"(x)); return r;
}
static __device__ __forceinline__ float lg2_approx(float x) {
    float r; asm("lg2.approx.f32 %0, %1;" : "=f"(r) : "f"(x)); return r;
}
// 1/x for x in [1, ~2^15]: bit-magic seed (~3.4% err) + 2 Newton steps (~1e-6).
// 1 alu + 4 fma-pipe ops; keeps the XU pipe free for EX2/LG2.
static __device__ __forceinline__ float fast_rcp(float x) {
    float y = __int_as_float(0x7EF311C2 - __float_as_int(x));
    y = y * fmaf(-x, y, 2.0f);
    y = y * fmaf(-x, y, 2.0f);
    return y;
}

#define LOG2E 1.44269504088896340f
#define LN2_D 0.6931471805599453094  // double, applied once at the end

// one pair-chain: softplus(lg-space) * weight, predicated accumulate
#define PAIR(xj, rj, xi, ri_, cond, acc)                  \
    {                                                     \
        float e_ = ex2_approx((xj) - (xi));               \
        float g_ = lg2_approx(1.0f + e_);                 \
        float w_ = fast_rcp((ri_) + (rj));                \
        if (cond) acc = fmaf(g_, w_, acc);                \
    }

__global__ void __launch_bounds__(THREADS)
wrnl_kernel(const float* __restrict__ logits,
            const int* __restrict__ rankings,   // JAX x64 disabled -> int32
            float* __restrict__ out,
            int n, int ntj, int nblocks) {
    const int t = threadIdx.x;
    const int k = blockIdx.x;

    // ---- decode block index k -> (ti, tj): ti over 256-row i-blocks,
    //      tj over 64-col j-blocks, tj >= 4*ti; off(ti) = ti*ntj - 2*ti*(ti-1)
    float c = (float)(ntj + 2);
    int ti = (int)((c - sqrtf(c * c - 16.0f * (float)k)) * 0.25f);
    while (ti > 0 && k < ti * ntj - 2 * ti * (ti - 1)) --ti;
    while (k >= (ti + 1) * ntj - 2 * (ti + 1) * ti) ++ti;
    const int tj = 4 * ti + (k - (ti * ntj - 2 * ti * (ti - 1)));
    const bool masked = (tj <= 4 * ti + 3);    // j-range overlaps i-range

    // j-tile, float4 per 2 j's: {x_{2b}, r_{2b}, x_{2b+1}, r_{2b+1}},
    // x_j = logit_j * log2e (f32).
    __shared__ float4 sJ[BJ / 2];

    // each thread owns two i-rows: gi0 = base+t, gi1 = base+t+128
    const int gi0 = ti * BI + t;
    const int gi1 = gi0 + 128;
    float x0, r0, x1, r1;
    if (gi0 < n) { x0 = logits[gi0] * LOG2E; r0 = (float)rankings[gi0]; }
    else         { x0 = 0.0f;                r0 = 3.0e9f; }   // never active
    if (gi1 < n) { x1 = logits[gi1] * LOG2E; r1 = (float)rankings[gi1]; }
    else         { x1 = 0.0f;                r1 = 3.0e9f; }

    if (t < BJ) {
        const int gj = tj * BJ + t;
        float xj, rj;
        if (gj < n) { xj = logits[gj] * LOG2E; rj = (float)rankings[gj]; }
        else        { xj = 0.0f;               rj = -1.0f; }  // inactive
        ((float2*)sJ)[t] = make_float2(xj, rj);
    }
    __syncthreads();

    float a00 = 0.0f, a01 = 0.0f, a02 = 0.0f, a03 = 0.0f;
    float a10 = 0.0f, a11 = 0.0f, a12 = 0.0f, a13 = 0.0f;

    if (!masked) {
        // fully interior: every (i,j) here has i<j; only the rank test gates.
        // 4 j's per iteration (2x LDS.128), 8 independent pair-chains.
        #pragma unroll
        for (int b = 0; b < BJ / 4; ++b) {
            float4 qa = sJ[2 * b];                   // j = 4b, 4b+1
            float4 qb = sJ[2 * b + 1];               // j = 4b+2, 4b+3
            PAIR(qa.x, qa.y, x0, r0, (r0 < qa.y), a00)
            PAIR(qa.z, qa.w, x0, r0, (r0 < qa.w), a01)
            PAIR(qb.x, qb.y, x0, r0, (r0 < qb.y), a02)
            PAIR(qb.z, qb.w, x0, r0, (r0 < qb.w), a03)
            PAIR(qa.x, qa.y, x1, r1, (r1 < qa.y), a10)
            PAIR(qa.z, qa.w, x1, r1, (r1 < qa.w), a11)
            PAIR(qb.x, qb.y, x1, r1, (r1 < qb.y), a12)
            PAIR(qb.z, qb.w, x1, r1, (r1 < qb.w), a13)
        }
    } else {
        // boundary blocks (tj in [4ti, 4ti+3]): additionally require gi < gj
        const int j0base = tj * BJ;
        #pragma unroll
        for (int b = 0; b < BJ / 4; ++b) {
            float4 qa = sJ[2 * b];
            float4 qb = sJ[2 * b + 1];
            int g0 = j0base + 4 * b;
            PAIR(qa.x, qa.y, x0, r0, ((r0 < qa.y) && (gi0 < g0)),     a00)
            PAIR(qa.z, qa.w, x0, r0, ((r0 < qa.w) && (gi0 < g0 + 1)), a01)
            PAIR(qb.x, qb.y, x0, r0, ((r0 < qb.y) && (gi0 < g0 + 2)), a02)
            PAIR(qb.z, qb.w, x0, r0, ((r0 < qb.w) && (gi0 < g0 + 3)), a03)
            PAIR(qa.x, qa.y, x1, r1, ((r1 < qa.y) && (gi1 < g0)),     a10)
            PAIR(qa.z, qa.w, x1, r1, ((r1 < qa.w) && (gi1 < g0 + 1)), a11)
            PAIR(qb.x, qb.y, x1, r1, ((r1 < qb.y) && (gi1 < g0 + 2)), a12)
            PAIR(qb.z, qb.w, x1, r1, ((r1 < qb.w) && (gi1 < g0 + 3)), a13)
        }
    }

    // ---- block reduction to one double partial ----
    float acc = ((a00 + a01) + (a02 + a03)) + ((a10 + a11) + (a12 + a13));
    #pragma unroll
    for (int off = 16; off > 0; off >>= 1)
        acc += __shfl_down_sync(0xffffffffu, acc, off);

    __shared__ float warpSum[4];
    __shared__ bool  isLast;
    if ((t & 31) == 0) warpSum[t >> 5] = acc;
    __syncthreads();
    if (t == 0) {
        double s = (double)warpSum[0] + (double)warpSum[1]
                 + (double)warpSum[2] + (double)warpSum[3];
        g_partials[k] = s;
        __threadfence();
        int old = atomicAdd(&g_count, 1);
        isLast = (old == nblocks - 1);
    }
    __syncthreads();
    if (!isLast) return;

    // ---- last block: deterministic final reduction ----
    __threadfence();
    double a = 0.0;
    for (int i = t; i < nblocks; i += THREADS) a += g_partials[i];
    #pragma unroll
    for (int off = 16; off > 0; off >>= 1)
        a += __shfl_down_sync(0xffffffffu, a, off);

    __shared__ double ws2[4];
    if ((t & 31) == 0) ws2[t >> 5] = a;
    __syncthreads();
    if (t == 0) {
        double s = ws2[0] + ws2[1] + ws2[2] + ws2[3];
        out[0] = (float)(s * LN2_D / (double)n);   // ln2 hoisted out of the whole sum
        g_count = 0;                               // reset for next graph replay
    }
}

extern "C" void kernel_launch(void* const* d_in, const int* in_sizes, int n_in,
                              void* d_out, int out_size) {
    const float* logits   = (const float*)d_in[0];
    const int*   rankings = (const int*)d_in[1];
    int n   = in_sizes[0];
    int nti = (n + BI - 1) / BI;             // 32 for N=8192
    int ntj = (n + BJ - 1) / BJ;             // 128 for N=8192

    // blocks: for each ti, tj runs [4*ti, ntj)
    int nblocks = 0;
    for (int ti = 0; ti < nti; ++ti) {
        int cnt = ntj - 4 * ti;
        if (cnt > 0) nblocks += cnt;
    }
    // == 2112 for N=8192

    wrnl_kernel<<<nblocks, THREADS>>>(logits, rankings, (float*)d_out, n, ntj, nblocks);
}